// round 14
// baseline (speedup 1.0000x reference)
#include <cuda_runtime.h>
#include <cuda_bf16.h>
#include <cstdint>

// Problem dims (fixed by the dataset)
#define T_STEPS 128
#define BATCH   128
#define D_IN    1024
#define D_OUT   1024
#define M_TOT   (T_STEPS * BATCH)   // 16384
#define BD      (BATCH * D_OUT)     // 131072

// GEMM tiling (FROZEN proven shape): 128x128 tile, 256 threads, TM=8 x TJ=4.
// Each GEMM CTA computes ONE K-half (512) of a tile. BM=128 => m-tile == t.
#define BM 128
#define BN 128
#define BK 16
#define TM 8
#define TJ 4
#define NTHREADS 256
#define NTILES   ((M_TOT / BM) * (D_OUT / BN))   // 1024 (128 t-tiles x 8 n-tiles)
#define NITER_H  (512 / BK)                      // 32 k-iters per half
#define NSCAN    256                             // scan CTAs appended at grid tail

// Scratch + flags (all __device__ globals; zero-init; self-cleaning per launch).
__device__ float    g_X[(size_t)M_TOT * D_OUT];
__device__ unsigned g_flag[NTILES];   // c0 ready   (set by c0, reset by c1)
__device__ unsigned g_done[NTILES];   // tile final (set by c1, reset by last scan reader)
__device__ unsigned g_cnt[8];         // per-bx scan completion counter

typedef unsigned long long ull;

__device__ __forceinline__ ull fma2(ull a, ull b, ull c) {
    ull d;
    asm("fma.rn.f32x2 %0, %1, %2, %3;" : "=l"(d) : "l"(a), "l"(b), "l"(c));
    return d;
}
__device__ __forceinline__ float2 unpack2(ull v) {
    float2 f;
    asm("mov.b64 {%0, %1}, %2;" : "=f"(f.x), "=f"(f.y) : "l"(v));
    return f;
}
__device__ __forceinline__ unsigned ld_acq(const unsigned* p) {
    unsigned v;
    asm volatile("ld.global.acquire.gpu.u32 %0, [%1];" : "=r"(v) : "l"(p) : "memory");
    return v;
}
__device__ __forceinline__ void st_rel(unsigned* p, unsigned v) {
    asm volatile("st.global.release.gpu.u32 [%0], %1;" :: "l"(p), "r"(v) : "memory");
}

// ---------------------------------------------------------------------------
// Fused kernel. bid < 1024: c0 half (k 0..511). 1024 <= bid < 2048: c1 half
// (k 512..1023) + combine ((c0+c1)+bias) [bit-exact frozen ordering].
// bid >= 2048: LIF scan CTA chasing c1 completion flags (producers all have
// lower bids -> started before any scan CTA is resident -> no deadlock).
// ---------------------------------------------------------------------------
__global__ __launch_bounds__(NTHREADS, 2)
void fused_gemm_scan_kernel(const float* __restrict__ A,
                            const float* __restrict__ W,
                            const float* __restrict__ bias,
                            float* __restrict__ out)
{
    __shared__ float As2[2][BK][2 * BM];   // duplicated A: 2 * 16KB
    __shared__ float Ws [2][BK][BN];       // 2 * 8KB

    const int bid = blockIdx.x;
    const int tid = threadIdx.x;

    if (bid >= 2 * NTILES) {
        // ================= scan CTA =================
        const int sid  = bid - 2 * NTILES;     // 0..255
        const int bx   = sid & 7;              // d-tile (0..7)
        const int bgrp = sid >> 3;             // b-group (0..31), 4 b-rows each
        const int l    = tid * 2;
        const int b    = bgrp * 4 + (l >> 7);
        const int d    = bx * 128 + (l & 127);
        const size_t off = (size_t)b * D_OUT + d;

        float2 u = make_float2(0.f, 0.f);
        for (int c = 0; c < 16; c++) {         // 16 chunks of 8 timesteps
            if (tid == 0) {
                #pragma unroll
                for (int j = 0; j < 8; j++) {
                    const unsigned* f = &g_done[(c * 8 + j) * 8 + bx];
                    while (ld_acq(f) == 0) __nanosleep(128);
                }
            }
            __syncthreads();
            #pragma unroll
            for (int j = 0; j < 8; j++) {
                int t = c * 8 + j;
                float2 x = *reinterpret_cast<const float2*>(
                    g_X + (size_t)t * BD + off);
                float2 s;
                u.x = __fadd_rn(__fmul_rn(0.75f, u.x), x.x);
                u.y = __fadd_rn(__fmul_rn(0.75f, u.y), x.y);
                s.x = (__fsub_rn(u.x, 1.0f) >= 0.0f) ? 1.0f : 0.0f;
                s.y = (__fsub_rn(u.y, 1.0f) >= 0.0f) ? 1.0f : 0.0f;
                *reinterpret_cast<float2*>(out + (size_t)t * BD + off) = s;
                u.x = __fsub_rn(u.x, s.x);
                u.y = __fsub_rn(u.y, s.y);
            }
        }
        __syncthreads();
        if (tid == 0) {
            // last of the 32 readers per bx resets that bx's flags + counter
            unsigned old = atomicAdd(&g_cnt[bx], 1u);
            if (old == 31u) {
                for (int t = 0; t < T_STEPS; t++) g_done[t * 8 + bx] = 0;
                __threadfence();
                g_cnt[bx] = 0;
            }
        }
        return;
    }

    // ================= GEMM half-tile CTA (FROZEN proven code) =================
    const bool is_c1 = (bid >= NTILES);
    const int tile  = is_c1 ? (bid - NTILES) : bid;
    const int bx    = tile & 7;            // N tile (0..7)
    const int by    = tile >> 3;           // M tile == timestep t (0..127)
    const int kbase = is_c1 ? 512 : 0;

    const int tx = tid & 15;               // n sub (0..15)
    const int ty = tid >> 4;               // m sub (0..15), m = ty*8 + i

    const float* Ablk = A + (size_t)by * BM * D_IN;

    const int a_row  = tid >> 2;           // 0..63 (+64)
    const int a_col4 = tid & 3;
    const int w_row  = tid >> 5;           // 0..7 (+8)
    const int w_col4 = tid & 31;

    float4 areg[2], wreg[2];

    auto load_tile = [&](int k0) {
        #pragma unroll
        for (int i = 0; i < 2; i++) {
            int r = a_row + i * 64;
            areg[i] = *reinterpret_cast<const float4*>(
                Ablk + (size_t)r * D_IN + k0 + a_col4 * 4);
        }
        #pragma unroll
        for (int i = 0; i < 2; i++) {
            int r = w_row + i * 8;
            wreg[i] = *reinterpret_cast<const float4*>(
                W + (size_t)(k0 + r) * D_OUT + (size_t)bx * BN + w_col4 * 4);
        }
    };
    auto store_tile = [&](int s) {
        #pragma unroll
        for (int i = 0; i < 2; i++) {
            int r = a_row + i * 64;
            *reinterpret_cast<float2*>(&As2[s][a_col4 * 4 + 0][2 * r]) =
                make_float2(areg[i].x, areg[i].x);
            *reinterpret_cast<float2*>(&As2[s][a_col4 * 4 + 1][2 * r]) =
                make_float2(areg[i].y, areg[i].y);
            *reinterpret_cast<float2*>(&As2[s][a_col4 * 4 + 2][2 * r]) =
                make_float2(areg[i].z, areg[i].z);
            *reinterpret_cast<float2*>(&As2[s][a_col4 * 4 + 3][2 * r]) =
                make_float2(areg[i].w, areg[i].w);
        }
        #pragma unroll
        for (int i = 0; i < 2; i++) {
            int r = w_row + i * 8;
            *reinterpret_cast<float4*>(&Ws[s][r][w_col4 * 4]) = wreg[i];
        }
    };

    ull acc2[TM][TJ];
    #pragma unroll
    for (int i = 0; i < TM; i++)
        #pragma unroll
        for (int j = 0; j < TJ; j++)
            acc2[i][j] = 0ULL;

    load_tile(kbase);
    store_tile(0);
    __syncthreads();
    int cur = 0;

    for (int it = 0; it < NITER_H; ++it) {
        if (it + 1 < NITER_H) load_tile(kbase + (it + 1) * BK);

        #pragma unroll
        for (int k = 0; k < BK; k++) {
            const ulonglong2* asrc = reinterpret_cast<const ulonglong2*>(
                &As2[cur][k][2 * (ty * TM)]);
            ull a2[TM];
            #pragma unroll
            for (int ii = 0; ii < 4; ii++) {
                ulonglong2 v = asrc[ii];
                a2[2 * ii + 0] = v.x;
                a2[2 * ii + 1] = v.y;
            }
            ull w2[TJ];
            #pragma unroll
            for (int j = 0; j < TJ; j++)
                w2[j] = *reinterpret_cast<const ull*>(
                    &Ws[cur][k][32 * j + 2 * tx]);
            #pragma unroll
            for (int i = 0; i < TM; i++)
                #pragma unroll
                for (int j = 0; j < TJ; j++)
                    acc2[i][j] = fma2(a2[i], w2[j], acc2[i][j]);
        }

        if (it + 1 < NITER_H) {
            store_tile(cur ^ 1);
            __syncthreads();
            cur ^= 1;
        }
    }

    if (!is_c1) {
        // c0 producer: store raw c0, publish with release flag.
        #pragma unroll
        for (int i = 0; i < TM; i++) {
            size_t row = (size_t)by * BM + ty * TM + i;
            #pragma unroll
            for (int j = 0; j < TJ; j++) {
                int col = bx * BN + 32 * j + 2 * tx;
                *reinterpret_cast<float2*>(g_X + row * D_OUT + col) =
                    unpack2(acc2[i][j]);
            }
        }
        __syncthreads();
        if (tid == 0) st_rel(&g_flag[tile], 1u);
    } else {
        // c1 consumer: wait for c0, combine ((c0+c1)+bias) with frozen
        // rounding, store final, reset c0-flag, publish done-flag for scan.
        if (tid == 0) {
            while (ld_acq(&g_flag[tile]) == 0) __nanosleep(64);
        }
        __syncthreads();

        #pragma unroll
        for (int i = 0; i < TM; i++) {
            size_t row = (size_t)by * BM + ty * TM + i;
            #pragma unroll
            for (int j = 0; j < TJ; j++) {
                int col = bx * BN + 32 * j + 2 * tx;
                float* dst = g_X + row * D_OUT + col;
                float2 c0;
                asm volatile("ld.global.cg.v2.f32 {%0, %1}, [%2];"
                             : "=f"(c0.x), "=f"(c0.y) : "l"(dst) : "memory");
                float2 c1 = unpack2(acc2[i][j]);
                float2 bv = *reinterpret_cast<const float2*>(bias + col);
                float2 o;
                o.x = __fadd_rn(__fadd_rn(c0.x, c1.x), bv.x);
                o.y = __fadd_rn(__fadd_rn(c0.y, c1.y), bv.y);
                *reinterpret_cast<float2*>(dst) = o;
            }
        }
        __syncthreads();
        if (tid == 0) {
            g_flag[tile] = 0;              // restore for next replay
            st_rel(&g_done[tile], 1u);     // release X-tile to scan CTAs
        }
    }
}

// ---------------------------------------------------------------------------
extern "C" void kernel_launch(void* const* d_in, const int* in_sizes, int n_in,
                              void* d_out, int out_size)
{
    const float* inputs = (const float*)d_in[0];   // [T, B, D_in]
    const float* W      = (const float*)d_in[1];   // [D_in, D_out]
    const float* bias   = (const float*)d_in[2];   // [D_out]
    float* out          = (float*)d_out;           // [T, B, D_out]

    fused_gemm_scan_kernel<<<2 * NTILES + NSCAN, NTHREADS>>>(inputs, W, bias, out);
}

// round 15
// speedup vs baseline: 1.0753x; 1.0753x over previous
#include <cuda_runtime.h>
#include <cuda_bf16.h>
#include <cstdint>

// Problem dims (fixed by the dataset)
#define T_STEPS 128
#define BATCH   128
#define D_IN    1024
#define D_OUT   1024
#define M_TOT   (T_STEPS * BATCH)   // 16384
#define BD      (BATCH * D_OUT)     // 131072

// GEMM tiling (FROZEN proven shape): 128x128 tile, 256 threads, TM=8 x TJ=4.
// Each GEMM CTA computes ONE K-half (512) of a tile.
#define BM 128
#define BN 128
#define BK 16
#define TM 8
#define TJ 4
#define NTHREADS 256
#define NTILES   ((M_TOT / BM) * (D_OUT / BN))   // 1024
#define NITER_H  (512 / BK)                      // 32 k-iters per half

// Scratch for X = A @ W + b (64 MB) + per-tile c0-ready flags.
__device__ float    g_X[(size_t)M_TOT * D_OUT];
__device__ unsigned g_flag[NTILES];              // zero-init; restored each launch

typedef unsigned long long ull;

__device__ __forceinline__ ull fma2(ull a, ull b, ull c) {
    ull d;
    asm("fma.rn.f32x2 %0, %1, %2, %3;" : "=l"(d) : "l"(a), "l"(b), "l"(c));
    return d;
}
__device__ __forceinline__ float2 unpack2(ull v) {
    float2 f;
    asm("mov.b64 {%0, %1}, %2;" : "=f"(f.x), "=f"(f.y) : "l"(v));
    return f;
}
__device__ __forceinline__ unsigned ld_acq(const unsigned* p) {
    unsigned v;
    asm volatile("ld.global.acquire.gpu.u32 %0, [%1];" : "=r"(v) : "l"(p) : "memory");
    return v;
}
__device__ __forceinline__ void st_rel(unsigned* p, unsigned v) {
    asm volatile("st.global.release.gpu.u32 [%0], %1;" :: "l"(p), "r"(v) : "memory");
}

// ---------------------------------------------------------------------------
// Kernel 1: X = A @ W + b with the bit-exact split-K=2 ordering (PROVEN):
//   c0 = serial ascending FFMA over k=0..511
//   c1 = serial ascending FFMA over k=512..1023
//   X  = ((c0 + c1) + bias), each add separately rounded.
// Grid = 2048 half-tile CTAs (R13 structure, proven). THIS ROUND: dup-A read
// as 8x LDS.64 broadcast (2 distinct 8B addrs/warp -> 1 wavefront each)
// instead of 4x LDS.128 (4 wavefronts each) -> L1 wavefronts 20 -> 12 per
// warp-kstep; fma pipe becomes the binding unit.
// ---------------------------------------------------------------------------
__global__ __launch_bounds__(NTHREADS, 2)
void sgemm_bias_splitk2_half_kernel(const float* __restrict__ A,
                                    const float* __restrict__ W,
                                    const float* __restrict__ bias)
{
    __shared__ float As2[2][BK][2 * BM];   // duplicated A: 2 * 16KB
    __shared__ float Ws [2][BK][BN];       // 2 * 8KB

    const int bid   = blockIdx.x;
    const bool is_c1 = (bid >= NTILES);
    const int tile  = is_c1 ? (bid - NTILES) : bid;
    const int bx    = tile & 7;            // N tile (0..7)
    const int by    = tile >> 3;           // M tile (0..127)
    const int kbase = is_c1 ? 512 : 0;

    const int tid = threadIdx.x;
    const int tx = tid & 15;               // n sub (0..15)
    const int ty = tid >> 4;               // m sub (0..15), m = ty*8 + i

    const float* Ablk = A + (size_t)by * BM * D_IN;

    const int a_row  = tid >> 2;           // 0..63 (+64)
    const int a_col4 = tid & 3;
    const int w_row  = tid >> 5;           // 0..7 (+8)
    const int w_col4 = tid & 31;

    float4 areg[2], wreg[2];

    auto load_tile = [&](int k0) {
        #pragma unroll
        for (int i = 0; i < 2; i++) {
            int r = a_row + i * 64;
            areg[i] = *reinterpret_cast<const float4*>(
                Ablk + (size_t)r * D_IN + k0 + a_col4 * 4);
        }
        #pragma unroll
        for (int i = 0; i < 2; i++) {
            int r = w_row + i * 8;
            wreg[i] = *reinterpret_cast<const float4*>(
                W + (size_t)(k0 + r) * D_OUT + (size_t)bx * BN + w_col4 * 4);
        }
    };
    auto store_tile = [&](int s) {
        #pragma unroll
        for (int i = 0; i < 2; i++) {
            int r = a_row + i * 64;
            *reinterpret_cast<float2*>(&As2[s][a_col4 * 4 + 0][2 * r]) =
                make_float2(areg[i].x, areg[i].x);
            *reinterpret_cast<float2*>(&As2[s][a_col4 * 4 + 1][2 * r]) =
                make_float2(areg[i].y, areg[i].y);
            *reinterpret_cast<float2*>(&As2[s][a_col4 * 4 + 2][2 * r]) =
                make_float2(areg[i].z, areg[i].z);
            *reinterpret_cast<float2*>(&As2[s][a_col4 * 4 + 3][2 * r]) =
                make_float2(areg[i].w, areg[i].w);
        }
        #pragma unroll
        for (int i = 0; i < 2; i++) {
            int r = w_row + i * 8;
            *reinterpret_cast<float4*>(&Ws[s][r][w_col4 * 4]) = wreg[i];
        }
    };

    // acc2[i][j]: m = by*BM + ty*8 + i;  n = bx*BN + 32*j + 2*tx + {lo,hi}
    ull acc2[TM][TJ];
    #pragma unroll
    for (int i = 0; i < TM; i++)
        #pragma unroll
        for (int j = 0; j < TJ; j++)
            acc2[i][j] = 0ULL;

    load_tile(kbase);
    store_tile(0);
    __syncthreads();
    int cur = 0;

    for (int it = 0; it < NITER_H; ++it) {
        if (it + 1 < NITER_H) load_tile(kbase + (it + 1) * BK);

        #pragma unroll
        for (int k = 0; k < BK; k++) {
            // dup-A: 8x LDS.64 broadcast (2 distinct 8B addrs per warp)
            const float* abase = &As2[cur][k][2 * (ty * TM)];
            ull a2[TM];
            #pragma unroll
            for (int i = 0; i < TM; i++)
                a2[i] = *reinterpret_cast<const ull*>(abase + 2 * i);
            // W: 4x LDS.64, banks 2*tx -> conflict-free
            ull w2[TJ];
            #pragma unroll
            for (int j = 0; j < TJ; j++)
                w2[j] = *reinterpret_cast<const ull*>(
                    &Ws[cur][k][32 * j + 2 * tx]);
            #pragma unroll
            for (int i = 0; i < TM; i++)
                #pragma unroll
                for (int j = 0; j < TJ; j++)
                    acc2[i][j] = fma2(a2[i], w2[j], acc2[i][j]);
        }

        if (it + 1 < NITER_H) {
            store_tile(cur ^ 1);
            __syncthreads();
            cur ^= 1;
        }
    }

    if (!is_c1) {
        // c0 producer: store raw c0, then publish with a release flag.
        #pragma unroll
        for (int i = 0; i < TM; i++) {
            size_t row = (size_t)by * BM + ty * TM + i;
            #pragma unroll
            for (int j = 0; j < TJ; j++) {
                int col = bx * BN + 32 * j + 2 * tx;
                *reinterpret_cast<float2*>(g_X + row * D_OUT + col) =
                    unpack2(acc2[i][j]);
            }
        }
        __syncthreads();
        if (tid == 0) st_rel(&g_flag[tile], 1u);
    } else {
        // c1 consumer: wait for c0 (acquire), combine ((c0+c1)+bias) with the
        // frozen rounding, store final, reset flag for the next replay.
        if (tid == 0) {
            while (ld_acq(&g_flag[tile]) == 0) __nanosleep(64);
        }
        __syncthreads();

        #pragma unroll
        for (int i = 0; i < TM; i++) {
            size_t row = (size_t)by * BM + ty * TM + i;
            #pragma unroll
            for (int j = 0; j < TJ; j++) {
                int col = bx * BN + 32 * j + 2 * tx;
                float* dst = g_X + row * D_OUT + col;
                float2 c0;
                asm volatile("ld.global.cg.v2.f32 {%0, %1}, [%2];"
                             : "=f"(c0.x), "=f"(c0.y) : "l"(dst) : "memory");
                float2 c1 = unpack2(acc2[i][j]);
                float2 bv = *reinterpret_cast<const float2*>(bias + col);
                float2 o;
                o.x = __fadd_rn(__fadd_rn(c0.x, c1.x), bv.x);
                o.y = __fadd_rn(__fadd_rn(c0.y, c1.y), bv.y);
                *reinterpret_cast<float2*>(dst) = o;
            }
        }
        __syncthreads();
        if (tid == 0) g_flag[tile] = 0;    // restore launch-invariant state
    }
}

// ---------------------------------------------------------------------------
// Kernel 2: LIF scan, 2 lanes per thread via float2, 256x256 (proven ~22us).
// ---------------------------------------------------------------------------
__global__ __launch_bounds__(256)
void lif_scan_v2_kernel(float* __restrict__ out)
{
    int idx = blockIdx.x * blockDim.x + threadIdx.x;   // 0 .. BD/2-1
    const float2* src = reinterpret_cast<const float2*>(g_X) + idx;
    float2* dst = reinterpret_cast<float2*>(out) + idx;
    const int stride2 = BD / 2;

    float2 u = make_float2(0.f, 0.f);
    #pragma unroll 8
    for (int t = 0; t < T_STEPS; t++) {
        float2 x = src[(size_t)t * stride2];
        float2 s;
        u.x = __fadd_rn(__fmul_rn(0.75f, u.x), x.x);
        u.y = __fadd_rn(__fmul_rn(0.75f, u.y), x.y);
        s.x = (__fsub_rn(u.x, 1.0f) >= 0.0f) ? 1.0f : 0.0f;
        s.y = (__fsub_rn(u.y, 1.0f) >= 0.0f) ? 1.0f : 0.0f;
        dst[(size_t)t * stride2] = s;
        u.x = __fsub_rn(u.x, s.x);
        u.y = __fsub_rn(u.y, s.y);
    }
}

// ---------------------------------------------------------------------------
extern "C" void kernel_launch(void* const* d_in, const int* in_sizes, int n_in,
                              void* d_out, int out_size)
{
    const float* inputs = (const float*)d_in[0];   // [T, B, D_in]
    const float* W      = (const float*)d_in[1];   // [D_in, D_out]
    const float* bias   = (const float*)d_in[2];   // [D_out]
    float* out          = (float*)d_out;           // [T, B, D_out]

    sgemm_bias_splitk2_half_kernel<<<2 * NTILES, NTHREADS>>>(inputs, W, bias);

    lif_scan_v2_kernel<<<(BD / 2) / 256, 256>>>(out);
}

// round 16
// speedup vs baseline: 1.0833x; 1.0074x over previous
#include <cuda_runtime.h>
#include <cuda_bf16.h>
#include <cstdint>

// Problem dims (fixed by the dataset)
#define T_STEPS 128
#define BATCH   128
#define D_IN    1024
#define D_OUT   1024
#define M_TOT   (T_STEPS * BATCH)   // 16384
#define BD      (BATCH * D_OUT)     // 131072

// GEMM tiling (FROZEN proven shape): 128x128 tile, 256 threads, TM=8 x TJ=4.
#define BM 128
#define BN 128
#define BK 16
#define TM 8
#define TJ 4
#define NTHREADS 256
#define NITER_H  (512 / BK)          // 32 k-iters per K-half

// Scratch for X = A @ W + b (64 MB) — __device__ global, no allocation.
__device__ float g_X[(size_t)M_TOT * D_OUT];

typedef unsigned long long ull;

__device__ __forceinline__ ull fma2(ull a, ull b, ull c) {
    ull d;
    asm("fma.rn.f32x2 %0, %1, %2, %3;" : "=l"(d) : "l"(a), "l"(b), "l"(c));
    return d;
}
__device__ __forceinline__ float2 unpack2(ull v) {
    float2 f;
    asm("mov.b64 {%0, %1}, %2;" : "=f"(f.x), "=f"(f.y) : "l"(v));
    return f;
}
__device__ __forceinline__ void cp_async16(void* smem, const void* g) {
    uint32_t sa = (uint32_t)__cvta_generic_to_shared(smem);
    asm volatile("cp.async.cg.shared.global [%0], [%1], 16;" :: "r"(sa), "l"(g));
}
__device__ __forceinline__ void cp_commit() {
    asm volatile("cp.async.commit_group;");
}
__device__ __forceinline__ void cp_wait0() {
    asm volatile("cp.async.wait_group 0;" ::: "memory");
}

// ---------------------------------------------------------------------------
// GEMM K-half kernel (templated): computes the serial ascending FFMA partial
// over k = KBASE..KBASE+511 (bit-exact frozen ordering).
//   IS_C1 == false: write raw c0 to g_X.
//   IS_C1 == true : read c0 (visible via kernel boundary), write
//                   ((c0 + c1) + bias) with the proven rounding sequence.
// W tile arrives via cp.async (no register staging); A via dup-transpose
// register path. __launch_bounds__(256,2): 2 CTAs/SM.
// ---------------------------------------------------------------------------
template<int KBASE, bool IS_C1>
__global__ __launch_bounds__(NTHREADS, 2)
void gemm_half_kernel(const float* __restrict__ A,
                      const float* __restrict__ W,
                      const float* __restrict__ bias)
{
    __shared__ float As2[2][BK][2 * BM];   // duplicated A: 2 * 16KB
    __shared__ float Ws [2][BK][BN];       // 2 * 8KB

    const int bx = blockIdx.x;             // N tile (0..7)
    const int by = blockIdx.y;             // M tile (0..127)
    const int tid = threadIdx.x;
    const int tx = tid & 15;               // n sub (0..15)
    const int ty = tid >> 4;               // m sub (0..15), m = ty*8 + i

    const float* Ablk = A + (size_t)by * BM * D_IN;

    const int a_row  = tid >> 2;           // 0..63 (+64)
    const int a_col4 = tid & 3;
    const int w_row  = tid >> 5;           // 0..7 (+8)
    const int w_col4 = tid & 31;

    float4 areg[2];

    auto load_a = [&](int k0) {
        #pragma unroll
        for (int i = 0; i < 2; i++) {
            int r = a_row + i * 64;
            areg[i] = *reinterpret_cast<const float4*>(
                Ablk + (size_t)r * D_IN + k0 + a_col4 * 4);
        }
    };
    auto store_a = [&](int s) {
        #pragma unroll
        for (int i = 0; i < 2; i++) {
            int r = a_row + i * 64;
            *reinterpret_cast<float2*>(&As2[s][a_col4 * 4 + 0][2 * r]) =
                make_float2(areg[i].x, areg[i].x);
            *reinterpret_cast<float2*>(&As2[s][a_col4 * 4 + 1][2 * r]) =
                make_float2(areg[i].y, areg[i].y);
            *reinterpret_cast<float2*>(&As2[s][a_col4 * 4 + 2][2 * r]) =
                make_float2(areg[i].z, areg[i].z);
            *reinterpret_cast<float2*>(&As2[s][a_col4 * 4 + 3][2 * r]) =
                make_float2(areg[i].w, areg[i].w);
        }
    };
    auto issue_w = [&](int k0, int s) {
        #pragma unroll
        for (int i = 0; i < 2; i++) {
            int r = w_row + i * 8;
            cp_async16(&Ws[s][r][w_col4 * 4],
                       W + (size_t)(k0 + r) * D_OUT + (size_t)bx * BN + w_col4 * 4);
        }
        cp_commit();
    };

    // acc2[i][j]: m = by*BM + ty*8 + i;  n = bx*BN + 32*j + 2*tx + {lo,hi}
    ull acc2[TM][TJ];
    #pragma unroll
    for (int i = 0; i < TM; i++)
        #pragma unroll
        for (int j = 0; j < TJ; j++)
            acc2[i][j] = 0ULL;

    // Prologue: tile 0 into buffer 0
    issue_w(KBASE, 0);
    load_a(KBASE);
    store_a(0);
    cp_wait0();
    __syncthreads();
    int cur = 0;

    for (int it = 0; it < NITER_H; ++it) {
        const bool more = (it + 1 < NITER_H);
        if (more) {
            issue_w(KBASE + (it + 1) * BK, cur ^ 1);
            load_a(KBASE + (it + 1) * BK);
        }

        #pragma unroll
        for (int k = 0; k < BK; k++) {
            // dup-A: 8x LDS.64 broadcast (2 distinct 8B addrs per warp)
            const float* abase = &As2[cur][k][2 * (ty * TM)];
            ull a2[TM];
            #pragma unroll
            for (int i = 0; i < TM; i++)
                a2[i] = *reinterpret_cast<const ull*>(abase + 2 * i);
            // W: 4x LDS.64, banks 2*tx -> conflict-free
            ull w2[TJ];
            #pragma unroll
            for (int j = 0; j < TJ; j++)
                w2[j] = *reinterpret_cast<const ull*>(
                    &Ws[cur][k][32 * j + 2 * tx]);
            #pragma unroll
            for (int i = 0; i < TM; i++)
                #pragma unroll
                for (int j = 0; j < TJ; j++)
                    acc2[i][j] = fma2(a2[i], w2[j], acc2[i][j]);
        }

        if (more) {
            store_a(cur ^ 1);
            cp_wait0();
            __syncthreads();
            cur ^= 1;
        }
    }

    if (!IS_C1) {
        // c0: store raw partial (kernel boundary publishes it).
        #pragma unroll
        for (int i = 0; i < TM; i++) {
            size_t row = (size_t)by * BM + ty * TM + i;
            #pragma unroll
            for (int j = 0; j < TJ; j++) {
                int col = bx * BN + 32 * j + 2 * tx;
                *reinterpret_cast<float2*>(g_X + row * D_OUT + col) =
                    unpack2(acc2[i][j]);
            }
        }
    } else {
        // c1: combine ((c0 + c1) + bias), each add separately rounded
        // (byte-identical to the proven epilogue).
        #pragma unroll
        for (int i = 0; i < TM; i++) {
            size_t row = (size_t)by * BM + ty * TM + i;
            #pragma unroll
            for (int j = 0; j < TJ; j++) {
                int col = bx * BN + 32 * j + 2 * tx;
                float* dst = g_X + row * D_OUT + col;
                float2 c0 = *reinterpret_cast<const float2*>(dst);
                float2 c1 = unpack2(acc2[i][j]);
                float2 bv = *reinterpret_cast<const float2*>(bias + col);
                float2 o;
                o.x = __fadd_rn(__fadd_rn(c0.x, c1.x), bv.x);
                o.y = __fadd_rn(__fadd_rn(c0.y, c1.y), bv.y);
                *reinterpret_cast<float2*>(dst) = o;
            }
        }
    }
}

// ---------------------------------------------------------------------------
// Kernel 2: LIF scan, 2 lanes per thread via float2, 256x256 (proven ~22us).
// ---------------------------------------------------------------------------
__global__ __launch_bounds__(256)
void lif_scan_v2_kernel(float* __restrict__ out)
{
    int idx = blockIdx.x * blockDim.x + threadIdx.x;   // 0 .. BD/2-1
    const float2* src = reinterpret_cast<const float2*>(g_X) + idx;
    float2* dst = reinterpret_cast<float2*>(out) + idx;
    const int stride2 = BD / 2;

    float2 u = make_float2(0.f, 0.f);
    #pragma unroll 8
    for (int t = 0; t < T_STEPS; t++) {
        float2 x = src[(size_t)t * stride2];
        float2 s;
        u.x = __fadd_rn(__fmul_rn(0.75f, u.x), x.x);
        u.y = __fadd_rn(__fmul_rn(0.75f, u.y), x.y);
        s.x = (__fsub_rn(u.x, 1.0f) >= 0.0f) ? 1.0f : 0.0f;
        s.y = (__fsub_rn(u.y, 1.0f) >= 0.0f) ? 1.0f : 0.0f;
        dst[(size_t)t * stride2] = s;
        u.x = __fsub_rn(u.x, s.x);
        u.y = __fsub_rn(u.y, s.y);
    }
}

// ---------------------------------------------------------------------------
extern "C" void kernel_launch(void* const* d_in, const int* in_sizes, int n_in,
                              void* d_out, int out_size)
{
    const float* inputs = (const float*)d_in[0];   // [T, B, D_in]
    const float* W      = (const float*)d_in[1];   // [D_in, D_out]
    const float* bias   = (const float*)d_in[2];   // [D_out]
    float* out          = (float*)d_out;           // [T, B, D_out]

    dim3 gemm_grid(D_OUT / BN, M_TOT / BM);        // (8, 128)
    gemm_half_kernel<0,   false><<<gemm_grid, NTHREADS>>>(inputs, W, bias);
    gemm_half_kernel<512, true ><<<gemm_grid, NTHREADS>>>(inputs, W, bias);

    lif_scan_v2_kernel<<<(BD / 2) / 256, 256>>>(out);
}

// round 17
// speedup vs baseline: 1.3875x; 1.2808x over previous
#include <cuda_runtime.h>
#include <cuda_bf16.h>
#include <cstdint>

// Problem dims (fixed by the dataset)
#define T_STEPS 128
#define BATCH   128
#define D_IN    1024
#define D_OUT   1024
#define M_TOT   (T_STEPS * BATCH)   // 16384
#define BD      (BATCH * D_OUT)     // 131072

// GEMM tiling (FROZEN proven shape): 128x128 tile, 256 threads, TM=8 x TJ=4.
#define BM 128
#define BN 128
#define BK 16
#define TM 8
#define TJ 4
#define NTHREADS 256
#define NITER_H  (512 / BK)          // 32 k-iters per K-half

// Scratch for X = A @ W + b (64 MB) — __device__ global, no allocation.
__device__ float g_X[(size_t)M_TOT * D_OUT];

typedef unsigned long long ull;

__device__ __forceinline__ ull fma2(ull a, ull b, ull c) {
    ull d;
    asm("fma.rn.f32x2 %0, %1, %2, %3;" : "=l"(d) : "l"(a), "l"(b), "l"(c));
    return d;
}
__device__ __forceinline__ float2 unpack2(ull v) {
    float2 f;
    asm("mov.b64 {%0, %1}, %2;" : "=f"(f.x), "=f"(f.y) : "l"(v));
    return f;
}
// Duplicate one fp32 into both halves of a packed f32x2 register (ALU pipe).
__device__ __forceinline__ ull pack_dup(float f) {
    ull d;
    asm("mov.b64 %0, {%1, %1};" : "=l"(d) : "f"(f));
    return d;
}
__device__ __forceinline__ void cp_async16(void* smem, const void* g) {
    uint32_t sa = (uint32_t)__cvta_generic_to_shared(smem);
    asm volatile("cp.async.cg.shared.global [%0], [%1], 16;" :: "r"(sa), "l"(g));
}
__device__ __forceinline__ void cp_commit() {
    asm volatile("cp.async.commit_group;");
}
__device__ __forceinline__ void cp_wait0() {
    asm volatile("cp.async.wait_group 0;" ::: "memory");
}

// ---------------------------------------------------------------------------
// GEMM K-half kernel: serial ascending FFMA partial over k=KBASE..KBASE+511
// (bit-exact frozen ordering; rel_err == 0.0 proven).
//   IS_C1 == false: write raw c0 to g_X.
//   IS_C1 == true : read c0, write ((c0 + c1) + bias), each add separately
//                   rounded (frozen epilogue).
// THIS ROUND: A tile stored PLAIN (no smem duplication). Per kstep each
// thread does 2x LDS.128 (broadcast) + 8x mov.b64 dup-packs (ALU) instead of
// 8x LDS.64 -> warp LDS wavefronts per kstep drop 12 -> 6; L1 unbinds.
// ---------------------------------------------------------------------------
template<int KBASE, bool IS_C1>
__global__ __launch_bounds__(NTHREADS, 2)
void gemm_half_kernel(const float* __restrict__ A,
                      const float* __restrict__ W,
                      const float* __restrict__ bias)
{
    __shared__ float As[2][BK][BM];        // plain transposed A: 2 * 8KB
    __shared__ float Ws[2][BK][BN];        // 2 * 8KB

    const int bx = blockIdx.x;             // N tile (0..7)
    const int by = blockIdx.y;             // M tile (0..127)
    const int tid = threadIdx.x;
    const int tx = tid & 15;               // n sub (0..15)
    const int ty = tid >> 4;               // m sub (0..15), m = ty*8 + i

    const float* Ablk = A + (size_t)by * BM * D_IN;

    const int a_row  = tid >> 2;           // 0..63 (+64)
    const int a_col4 = tid & 3;
    const int w_row  = tid >> 5;           // 0..7 (+8)
    const int w_col4 = tid & 31;

    float4 areg[2];

    auto load_a = [&](int k0) {
        #pragma unroll
        for (int i = 0; i < 2; i++) {
            int r = a_row + i * 64;
            areg[i] = *reinterpret_cast<const float4*>(
                Ablk + (size_t)r * D_IN + k0 + a_col4 * 4);
        }
    };
    auto store_a = [&](int s) {
        // plain transpose: As[k][m] = A[m][k]  (8 scalar STS, half the bytes
        // of the old dup-store)
        #pragma unroll
        for (int i = 0; i < 2; i++) {
            int r = a_row + i * 64;
            As[s][a_col4 * 4 + 0][r] = areg[i].x;
            As[s][a_col4 * 4 + 1][r] = areg[i].y;
            As[s][a_col4 * 4 + 2][r] = areg[i].z;
            As[s][a_col4 * 4 + 3][r] = areg[i].w;
        }
    };
    auto issue_w = [&](int k0, int s) {
        #pragma unroll
        for (int i = 0; i < 2; i++) {
            int r = w_row + i * 8;
            cp_async16(&Ws[s][r][w_col4 * 4],
                       W + (size_t)(k0 + r) * D_OUT + (size_t)bx * BN + w_col4 * 4);
        }
        cp_commit();
    };

    // acc2[i][j]: m = by*BM + ty*8 + i;  n = bx*BN + 32*j + 2*tx + {lo,hi}
    ull acc2[TM][TJ];
    #pragma unroll
    for (int i = 0; i < TM; i++)
        #pragma unroll
        for (int j = 0; j < TJ; j++)
            acc2[i][j] = 0ULL;

    // Prologue: tile 0 into buffer 0
    issue_w(KBASE, 0);
    load_a(KBASE);
    store_a(0);
    cp_wait0();
    __syncthreads();
    int cur = 0;

    for (int it = 0; it < NITER_H; ++it) {
        const bool more = (it + 1 < NITER_H);
        if (more) {
            issue_w(KBASE + (it + 1) * BK, cur ^ 1);
            load_a(KBASE + (it + 1) * BK);
        }

        #pragma unroll
        for (int k = 0; k < BK; k++) {
            // A: 2x LDS.128 broadcast (2 distinct 16B addrs per warp),
            // then dup-pack in ALU regs.
            const float4* abase = reinterpret_cast<const float4*>(
                &As[cur][k][ty * TM]);
            float4 fa0 = abase[0];
            float4 fa1 = abase[1];
            ull a2[TM];
            a2[0] = pack_dup(fa0.x); a2[1] = pack_dup(fa0.y);
            a2[2] = pack_dup(fa0.z); a2[3] = pack_dup(fa0.w);
            a2[4] = pack_dup(fa1.x); a2[5] = pack_dup(fa1.y);
            a2[6] = pack_dup(fa1.z); a2[7] = pack_dup(fa1.w);
            // W: 4x LDS.64, banks 2*tx -> conflict-free
            ull w2[TJ];
            #pragma unroll
            for (int j = 0; j < TJ; j++)
                w2[j] = *reinterpret_cast<const ull*>(
                    &Ws[cur][k][32 * j + 2 * tx]);
            #pragma unroll
            for (int i = 0; i < TM; i++)
                #pragma unroll
                for (int j = 0; j < TJ; j++)
                    acc2[i][j] = fma2(a2[i], w2[j], acc2[i][j]);
        }

        if (more) {
            store_a(cur ^ 1);
            cp_wait0();
            __syncthreads();
            cur ^= 1;
        }
    }

    if (!IS_C1) {
        // c0: store raw partial (kernel boundary publishes it).
        #pragma unroll
        for (int i = 0; i < TM; i++) {
            size_t row = (size_t)by * BM + ty * TM + i;
            #pragma unroll
            for (int j = 0; j < TJ; j++) {
                int col = bx * BN + 32 * j + 2 * tx;
                *reinterpret_cast<float2*>(g_X + row * D_OUT + col) =
                    unpack2(acc2[i][j]);
            }
        }
    } else {
        // c1: combine ((c0 + c1) + bias), each add separately rounded
        // (byte-identical to the proven epilogue).
        #pragma unroll
        for (int i = 0; i < TM; i++) {
            size_t row = (size_t)by * BM + ty * TM + i;
            #pragma unroll
            for (int j = 0; j < TJ; j++) {
                int col = bx * BN + 32 * j + 2 * tx;
                float* dst = g_X + row * D_OUT + col;
                float2 c0 = *reinterpret_cast<const float2*>(dst);
                float2 c1 = unpack2(acc2[i][j]);
                float2 bv = *reinterpret_cast<const float2*>(bias + col);
                float2 o;
                o.x = __fadd_rn(__fadd_rn(c0.x, c1.x), bv.x);
                o.y = __fadd_rn(__fadd_rn(c0.y, c1.y), bv.y);
                *reinterpret_cast<float2*>(dst) = o;
            }
        }
    }
}

// ---------------------------------------------------------------------------
// Kernel 2: LIF scan, 2 lanes per thread via float2, 256x256 (proven ~22us).
// ---------------------------------------------------------------------------
__global__ __launch_bounds__(256)
void lif_scan_v2_kernel(float* __restrict__ out)
{
    int idx = blockIdx.x * blockDim.x + threadIdx.x;   // 0 .. BD/2-1
    const float2* src = reinterpret_cast<const float2*>(g_X) + idx;
    float2* dst = reinterpret_cast<float2*>(out) + idx;
    const int stride2 = BD / 2;

    float2 u = make_float2(0.f, 0.f);
    #pragma unroll 8
    for (int t = 0; t < T_STEPS; t++) {
        float2 x = src[(size_t)t * stride2];
        float2 s;
        u.x = __fadd_rn(__fmul_rn(0.75f, u.x), x.x);
        u.y = __fadd_rn(__fmul_rn(0.75f, u.y), x.y);
        s.x = (__fsub_rn(u.x, 1.0f) >= 0.0f) ? 1.0f : 0.0f;
        s.y = (__fsub_rn(u.y, 1.0f) >= 0.0f) ? 1.0f : 0.0f;
        dst[(size_t)t * stride2] = s;
        u.x = __fsub_rn(u.x, s.x);
        u.y = __fsub_rn(u.y, s.y);
    }
}

// ---------------------------------------------------------------------------
extern "C" void kernel_launch(void* const* d_in, const int* in_sizes, int n_in,
                              void* d_out, int out_size)
{
    const float* inputs = (const float*)d_in[0];   // [T, B, D_in]
    const float* W      = (const float*)d_in[1];   // [D_in, D_out]
    const float* bias   = (const float*)d_in[2];   // [D_out]
    float* out          = (float*)d_out;           // [T, B, D_out]

    dim3 gemm_grid(D_OUT / BN, M_TOT / BM);        // (8, 128)
    gemm_half_kernel<0,   false><<<gemm_grid, NTHREADS>>>(inputs, W, bias);
    gemm_half_kernel<512, true ><<<gemm_grid, NTHREADS>>>(inputs, W, bias);

    lif_scan_v2_kernel<<<(BD / 2) / 256, 256>>>(out);
}